// round 17
// baseline (speedup 1.0000x reference)
#include <cuda_runtime.h>
#include <cuda_fp16.h>
#include <cstdint>

#define CB   4
#define CN   2048
#define CH   8
#define CDH  64
#define CDIM 512
#define ATT_SCALE 0.125f
#define SSTR 72            // smem row stride in fp16 (64 data + 8 pad) = 144B

typedef __half h16;

// ---------------- scratch (__device__ globals; no allocation allowed) -------
__device__ h16 g_xf[CB * CN * CDIM];
__device__ h16 g_qf[CB * CN * CDIM];
__device__ h16 g_kf[CB * CN * CDIM];    // compacted K rows
__device__ h16 g_vf[CB * CN * CDIM];    // compacted V rows
__device__ h16 g_of[CB * CN * CDIM];
__device__ h16 g_wf[4][CDIM * CDIM];
__device__ int  g_idx[CB * CN];
__device__ int  g_cnt[CB];
__device__ float g_sv[CB * CDIM];
__device__ float g_xmp[CB * 32 * CDIM]; // masked-x partial sums (per 64-row segment)

// ---------------- helpers ----------------------------------------------------
__device__ __forceinline__ void mma16816(float* c, const uint32_t* a, uint32_t b0, uint32_t b1) {
    asm volatile(
        "mma.sync.aligned.m16n8k16.row.col.f32.f16.f16.f32 "
        "{%0,%1,%2,%3}, {%4,%5,%6,%7}, {%8,%9}, {%0,%1,%2,%3};\n"
        : "+f"(c[0]), "+f"(c[1]), "+f"(c[2]), "+f"(c[3])
        : "r"(a[0]), "r"(a[1]), "r"(a[2]), "r"(a[3]), "r"(b0), "r"(b1));
}
__device__ __forceinline__ void ldsm_x4(uint32_t& r0, uint32_t& r1, uint32_t& r2, uint32_t& r3,
                                        uint32_t saddr) {
    asm volatile("ldmatrix.sync.aligned.m8n8.x4.shared.b16 {%0,%1,%2,%3}, [%4];"
                 : "=r"(r0), "=r"(r1), "=r"(r2), "=r"(r3) : "r"(saddr));
}
__device__ __forceinline__ void ldsm_x2_t(uint32_t& r0, uint32_t& r1, uint32_t saddr) {
    asm volatile("ldmatrix.sync.aligned.m8n8.x2.trans.shared.b16 {%0,%1}, [%2];"
                 : "=r"(r0), "=r"(r1) : "r"(saddr));
}
__device__ __forceinline__ uint32_t packh(h16 x, h16 y) {
    __half2 t = __halves2half2(x, y);
    return *reinterpret_cast<uint32_t*>(&t);
}
__device__ __forceinline__ uint32_t smem_u32(const void* p) {
    uint32_t a;
    asm("{ .reg .u64 t; cvta.to.shared.u64 t, %1; cvt.u32.u64 %0, t; }" : "=r"(a) : "l"(p));
    return a;
}
__device__ __forceinline__ void cp_async16(uint32_t saddr, const void* g) {
    asm volatile("cp.async.cg.shared.global [%0], [%1], 16;" :: "r"(saddr), "l"(g));
}
__device__ __forceinline__ void cp_commit() { asm volatile("cp.async.commit_group;"); }
template<int N> __device__ __forceinline__ void cp_wait() {
    asm volatile("cp.async.wait_group %0;" :: "n"(N));
}

// ---------------- ONE prep launch: convert + scan + masked-x partials --------
__global__ void prep_all_kernel(const float* __restrict__ x,
                                const float* __restrict__ w0, const float* __restrict__ w1,
                                const float* __restrict__ w2, const float* __restrict__ w3,
                                const int* __restrict__ mask,
                                h16* __restrict__ xf, h16* __restrict__ wf,
                                int* __restrict__ idxl, int* __restrict__ cnt,
                                float* __restrict__ xmp)
{
    const int NXc = CB * CN * CDIM;
    const int NWc = CDIM * CDIM;
    const int NB  = (NXc + 4 * NWc) / 1024;
    const int t   = threadIdx.x;

    if ((int)blockIdx.x < NB) {
        int i = (blockIdx.x * blockDim.x + t) * 4;
        const float* src;
        h16* dst;
        if (i < NXc) {
            src = x + i;
            dst = xf + i;
        } else {
            int j = i - NXc;
            int w = j / NWc, o = j - w * NWc;
            src = ((w == 0) ? w0 : (w == 1) ? w1 : (w == 2) ? w2 : w3) + o;
            dst = wf + (size_t)w * NWc + o;
        }
        float4 v = *(const float4*)src;
        *(uint32_t*)(dst)     = packh(__float2half_rn(v.x), __float2half_rn(v.y));
        *(uint32_t*)(dst + 2) = packh(__float2half_rn(v.z), __float2half_rn(v.w));
    } else if ((int)blockIdx.x < NB + CB) {
        __shared__ int ps[256];
        const int b = blockIdx.x - NB;
        int loc[8], c = 0;
#pragma unroll
        for (int i = 0; i < 8; i++) {
            loc[i] = c;
            c += (mask[b * CN + t * 8 + i] != 0);
        }
        ps[t] = c;
        __syncthreads();
        for (int off = 1; off < 256; off <<= 1) {
            int v = (t >= off) ? ps[t - off] : 0;
            __syncthreads();
            ps[t] += v;
            __syncthreads();
        }
        int excl = ps[t] - c;
#pragma unroll
        for (int i = 0; i < 8; i++)
            if (mask[b * CN + t * 8 + i] != 0)
                idxl[b * CN + excl + loc[i]] = t * 8 + i;
        if (t == 255) cnt[b] = ps[255];
    } else {
        int idx   = blockIdx.x - NB - CB;     // 0..255
        int chalf = idx & 1;
        int b     = (idx >> 1) & 3;
        int seg   = idx >> 3;                 // 0..31
        int c     = chalf * 256 + t;
        int r0    = seg * 64;
        float s = 0.f;
#pragma unroll 4
        for (int i = 0; i < 64; i++) {
            int row = r0 + i;
            if (mask[b * CN + row] == 0)
                s += x[(size_t)(b * CN + row) * CDIM + c];
        }
        xmp[((size_t)b * 32 + seg) * CDIM + c] = s;
    }
}

// ---------------- GEMM mainloop: 1-pass fp16, 3-stage, ldmatrix frags --------
#define TEN_B   (128 * SSTR * 2)
#define STAGE_B (2 * TEN_B)

#define GEMM_LOAD_CHUNK(st, kc)                                                   \
    {                                                                             \
        _Pragma("unroll")                                                         \
        for (int i = 0; i < 4; i++) {                                             \
            int idx = tid + 256 * i;                                              \
            int r = idx >> 3, u = idx & 7;                                        \
            uint32_t so = sbase + (uint32_t)((st) * STAGE_B + (r * SSTR + 8 * u) * 2); \
            cp_async16(so + 0 * TEN_B, Af_g + (size_t)(rowBase + r) * CDIM + (kc) + 8 * u); \
            cp_async16(so + 1 * TEN_B, Bf_g + (size_t)(colBase + r) * CDIM + (kc) + 8 * u); \
        }                                                                         \
        cp_commit();                                                              \
    }

#define KV_LOAD_CHUNK(st, kc)                                                     \
    {                                                                             \
        _Pragma("unroll")                                                         \
        for (int i = 0; i < 4; i++) {                                             \
            int idx = tid + 256 * i;                                              \
            int r = idx >> 3, u = idx & 7;                                        \
            uint32_t so = sbase + (uint32_t)((st) * STAGE_B + (r * SSTR + 8 * u) * 2); \
            cp_async16(so + 0 * TEN_B, Af_g + (size_t)(b * CN + toks[i]) * CDIM + (kc) + 8 * u); \
            cp_async16(so + 1 * TEN_B, Bf_g + (size_t)(colBase + r) * CDIM + (kc) + 8 * u); \
        }                                                                         \
        cp_commit();                                                              \
    }

// A x4: lanes (row = lane&15, khalf = lane>>4); B x4: lanes (row = ((lane>>4)<<3)|(lane&7),
// khalf = (lane>>3)&1) -> {b0_j, b1_j, b0_j+1, b1_j+1}.
#define GEMM_COMPUTE_CHUNK(st)                                                    \
    {                                                                             \
        const uint32_t abase = sbase + (uint32_t)((st) * STAGE_B)                 \
            + (uint32_t)(((32 * wM + arow) * SSTR + akoff) * 2);                  \
        const uint32_t bbase = sbase + (uint32_t)((st) * STAGE_B + TEN_B)         \
            + (uint32_t)(((64 * wN + brow) * SSTR + bkoff) * 2);                  \
        _Pragma("unroll")                                                         \
        for (int ka = 0; ka < 4; ka++) {                                          \
            uint32_t af[2][4];                                                    \
            ldsm_x4(af[0][0], af[0][1], af[0][2], af[0][3], abase + ka * 32);     \
            ldsm_x4(af[1][0], af[1][1], af[1][2], af[1][3],                       \
                    abase + ka * 32 + (uint32_t)(16 * SSTR * 2));                 \
            _Pragma("unroll")                                                     \
            for (int jj = 0; jj < 4; jj++) {                                      \
                uint32_t b0, b1, b2, b3;                                          \
                ldsm_x4(b0, b1, b2, b3,                                           \
                        bbase + ka * 32 + (uint32_t)(jj * 16 * SSTR * 2));        \
                mma16816(acc[0][2 * jj],     af[0], b0, b1);                      \
                mma16816(acc[1][2 * jj],     af[1], b0, b1);                      \
                mma16816(acc[0][2 * jj + 1], af[0], b2, b3);                      \
                mma16816(acc[1][2 * jj + 1], af[1], b2, b3);                      \
            }                                                                     \
        }                                                                         \
    }

#define GEMM_PREAMBLE()                                                           \
    const int tid  = threadIdx.x;                                                 \
    const int w    = tid >> 5;                                                    \
    const int lane = tid & 31;                                                    \
    const int g    = lane >> 2;                                                   \
    const int tig  = lane & 3;                                                    \
    const int wM   = w >> 1;                                                      \
    const int wN   = w & 1;                                                       \
    const int arow = lane & 15;                                                   \
    const int akoff = 8 * (lane >> 4);                                            \
    const int brow = ((lane >> 4) << 3) | (lane & 7);                             \
    const int bkoff = 8 * ((lane >> 3) & 1);                                      \
    float acc[2][8][4];                                                           \
    _Pragma("unroll")                                                             \
    for (int m = 0; m < 2; m++)                                                   \
        _Pragma("unroll")                                                         \
        for (int j = 0; j < 8; j++)                                               \
            _Pragma("unroll")                                                     \
            for (int t = 0; t < 4; t++) acc[m][j][t] = 0.f;

#define GEMM_MAINLOOP(LOADM)                                                      \
    LOADM(0, 0)                                                                   \
    LOADM(1, 64)                                                                  \
    _Pragma("unroll 1")                                                           \
    for (int ch = 0; ch < 8; ch++) {                                              \
        if (ch < 6) cp_wait<1>(); else cp_wait<0>();                              \
        __syncthreads();                                                          \
        if (ch + 2 < 8) LOADM((ch + 2) % 3, 64 * (ch + 2))                        \
        GEMM_COMPUTE_CHUNK(ch % 3)                                                \
    }

#define GEMM_EPI_SINGLE(outF, rowB, scale)                                        \
    _Pragma("unroll")                                                             \
    for (int m = 0; m < 2; m++)                                                   \
        _Pragma("unroll")                                                         \
        for (int j = 0; j < 8; j++) {                                             \
            int row = (rowB) + 32 * wM + 16 * m + g;                              \
            int col = colBase + 64 * wN + 8 * j + 2 * tig;                        \
            *(uint32_t*)&(outF)[(size_t)row * CDIM + col] =                       \
                packh(__float2half_rn(acc[m][j][0] * (scale)),                    \
                      __float2half_rn(acc[m][j][1] * (scale)));                   \
            *(uint32_t*)&(outF)[(size_t)(row + 8) * CDIM + col] =                 \
                packh(__float2half_rn(acc[m][j][2] * (scale)),                    \
                      __float2half_rn(acc[m][j][3] * (scale)));                   \
        }

// ---------------- fused Q + compacted-K/V projection + sv GEMV ---------------
__global__ __launch_bounds__(256, 2) void proj_gemm_kernel(
    const h16* __restrict__ Af_g,
    const h16* __restrict__ wq, const h16* __restrict__ wk, const h16* __restrict__ wv,
    const float* __restrict__ Wv32, const float* __restrict__ xmp,
    const int* __restrict__ idxl, const int* __restrict__ cntp,
    h16* __restrict__ qf, h16* __restrict__ kcf, h16* __restrict__ vcf,
    float* __restrict__ sv)
{
    extern __shared__ h16 gs[];
    const uint32_t sbase = smem_u32(gs);

    if (blockIdx.x == 12) {
        float* xsum = (float*)gs;
        const int b      = blockIdx.y >> 4;
        const int nchunk = blockIdx.y & 15;
        const int t = threadIdx.x;
#pragma unroll
        for (int p = 0; p < 2; p++) {
            int c = t + 256 * p;
            float s = 0.f;
#pragma unroll 8
            for (int seg = 0; seg < 32; seg++)
                s += xmp[((size_t)b * 32 + seg) * CDIM + c];
            xsum[c] = s;
        }
        __syncthreads();
        const int warp = t >> 5, lane = t & 31;
#pragma unroll
        for (int i = 0; i < 4; i++) {
            int n = nchunk * 32 + warp * 4 + i;
            const float* wr = Wv32 + (size_t)n * CDIM;
            float s = 0.f;
#pragma unroll
            for (int c = lane * 4; c < CDIM; c += 128) {
                float4 wv = *(const float4*)(wr + c);
                float4 xv = *(const float4*)(xsum + c);
                s += wv.x * xv.x + wv.y * xv.y + wv.z * xv.z + wv.w * xv.w;
            }
            s += __shfl_xor_sync(0xffffffffu, s, 16);
            s += __shfl_xor_sync(0xffffffffu, s, 8);
            s += __shfl_xor_sync(0xffffffffu, s, 4);
            s += __shfl_xor_sync(0xffffffffu, s, 2);
            s += __shfl_xor_sync(0xffffffffu, s, 1);
            if (lane == 0) sv[b * CDIM + n] = s;
        }
        return;
    }

    if (blockIdx.x < 4) {
        const int colBase = blockIdx.x * 128;
        const int rowBase = blockIdx.y * 128;
        const h16* Bf_g = wq;
        GEMM_PREAMBLE()
        GEMM_MAINLOOP(GEMM_LOAD_CHUNK)
        GEMM_EPI_SINGLE(qf, rowBase, ATT_SCALE)
    } else {
        const int xx      = blockIdx.x - 4;
        const int wsel    = xx >> 2;
        const int colBase = (xx & 3) * 128;
        const int b       = blockIdx.y >> 4;
        const int tile    = blockIdx.y & 15;
        const int cnt1    = cntp[b];
        const int kend    = (cnt1 + 63) & ~63;
        if (tile * 128 >= kend) return;
        const int* bidx = idxl + b * CN;
        const h16* Bf_g = wsel ? wv : wk;

        GEMM_PREAMBLE()

        int toks[4];
#pragma unroll
        for (int i = 0; i < 4; i++) {
            int r = (tid + 256 * i) >> 3;
            int jj = tile * 128 + r;
            toks[i] = bidx[jj < cnt1 ? jj : cnt1 - 1];
        }

        GEMM_MAINLOOP(KV_LOAD_CHUNK)

        const int rowB = b * CN + tile * 128;
        if (wsel == 0) {
            GEMM_EPI_SINGLE(kcf, rowB, 1.0f)
        } else {
            GEMM_EPI_SINGLE(vcf, rowB, 1.0f)
        }
    }
}

// ---------------- output projection (1-pass, fp32 out) -----------------------
__global__ __launch_bounds__(256, 2) void out_gemm_kernel(
    const h16* __restrict__ Af_g, const h16* __restrict__ Bf_g, float* __restrict__ C)
{
    extern __shared__ h16 gs[];
    const uint32_t sbase = smem_u32(gs);
    const int colBase = blockIdx.x * 128;
    const int rowBase = blockIdx.y * 128;

    GEMM_PREAMBLE()
    GEMM_MAINLOOP(GEMM_LOAD_CHUNK)

#pragma unroll
    for (int m = 0; m < 2; m++)
#pragma unroll
        for (int j = 0; j < 8; j++) {
            int row = rowBase + 32 * wM + 16 * m + g;
            int col = colBase + 64 * wN + 8 * j + 2 * tig;
            *(float2*)&C[(size_t)row * CDIM + col]       = make_float2(acc[m][j][0], acc[m][j][1]);
            *(float2*)&C[(size_t)(row + 8) * CDIM + col] = make_float2(acc[m][j][2], acc[m][j][3]);
        }
}

// ---------------- flash attention: 1-pass, 3-stage, ldmatrix K ---------------
#define ATEN (64 * SSTR)
#define ASTG (2 * ATEN)                 // kf, vf

__global__ __launch_bounds__(256, 2) void attn_mma_kernel(
    const h16* __restrict__ qf_g,
    const h16* __restrict__ kf_g, const h16* __restrict__ vf_g,
    const int* __restrict__ cntp, const float* __restrict__ sv,
    h16* __restrict__ OF)
{
    extern __shared__ h16 sm[];        // [3 stages][2 tensors][64*SSTR] + Q staging
    h16* Qs = sm + 3 * ASTG;

    const uint32_t sbase = smem_u32(sm);
    const int tid  = threadIdx.x;
    const int w    = tid >> 5;
    const int lane = tid & 31;
    const int g    = lane >> 2;
    const int tig  = lane & 3;
    const int q0   = blockIdx.x * 128;
    const int h    = blockIdx.y & 7;
    const int b    = blockIdx.y >> 3;
    const int cb   = h * CDH;

    const int cnt1 = cntp[b];
    const int cnt0 = CN - cnt1;
    const int nt   = (cnt1 + 63) >> 6;

    const int arow = lane & 15;
    const int akoff = 8 * (lane >> 4);
    const int brow = ((lane >> 4) << 3) | (lane & 7);
    const int bkoff = 8 * ((lane >> 3) & 1);
    const uint32_t lrow = (uint32_t)(lane & 15) * SSTR * 2;

#define ATT_LOAD(st, kb_)                                                          \
    {                                                                              \
        _Pragma("unroll")                                                          \
        for (int i = 0; i < 2; i++) {                                              \
            int idx = tid + 256 * i;          /* 0..511 */                         \
            int r = idx >> 3, u = idx & 7;                                         \
            size_t grow = (size_t)(b * CN + (kb_) + r) * CDIM + cb + 8 * u;        \
            uint32_t so = sbase + (uint32_t)(((st) * ASTG + r * SSTR + 8 * u) * 2);\
            cp_async16(so + 0 * ATEN * 2, kf_g + grow);                            \
            cp_async16(so + 1 * ATEN * 2, vf_g + grow);                            \
        }                                                                          \
        cp_commit();                                                               \
    }

    if (nt > 0) ATT_LOAD(0, 0)
    if (nt > 1) ATT_LOAD(1, 64)

    // ---- preload Q fragments via shared staging (ldmatrix) ----
    uint32_t qf[4][4];
    {
#pragma unroll
        for (int i = 0; i < 4; i++) {
            int idx = tid + 256 * i;
            int r = idx >> 3, u = idx & 7;
            *(uint4*)&Qs[r * SSTR + 8 * u] =
                *((const uint4*)(qf_g + (size_t)(b * CN + q0 + r) * CDIM + cb) + u);
        }
        __syncthreads();
        const uint32_t qbase = sbase + (uint32_t)(3 * ASTG * 2)
            + (uint32_t)(((16 * w + arow) * SSTR + akoff) * 2);
#pragma unroll
        for (int ka = 0; ka < 4; ka++)
            ldsm_x4(qf[ka][0], qf[ka][1], qf[ka][2], qf[ka][3], qbase + ka * 32);
    }

    float o[8][4];
#pragma unroll
    for (int n = 0; n < 8; n++)
#pragma unroll
        for (int t = 0; t < 4; t++) o[n][t] = 0.f;
    float m0 = -1e30f, m1 = -1e30f, l0 = 0.f, l1 = 0.f;

#pragma unroll 1
    for (int it = 0; it < nt; it++) {
        const int kb = it * 64;
        const int st = it % 3;
        if (it < nt - 2) cp_wait<1>(); else cp_wait<0>();
        __syncthreads();
        if (it + 2 < nt) ATT_LOAD((it + 2) % 3, kb + 128)

        const uint32_t kbase = sbase + (uint32_t)(st * ASTG * 2)
            + (uint32_t)((brow * SSTR + bkoff) * 2);
        const uint32_t vfb = sbase + (uint32_t)((st * ASTG + ATEN) * 2) + lrow;

        // ---- S = Q K^T (1-pass, ldmatrix.x4 K-frags) ----
        float s[8][4];
#pragma unroll
        for (int j = 0; j < 8; j++)
#pragma unroll
            for (int t = 0; t < 4; t++) s[j][t] = 0.f;
#pragma unroll
        for (int ka = 0; ka < 4; ka++) {
#pragma unroll
            for (int jj = 0; jj < 4; jj++) {
                uint32_t b0, b1, b2, b3;
                ldsm_x4(b0, b1, b2, b3,
                        kbase + ka * 32 + (uint32_t)(jj * 16 * SSTR * 2));
                mma16816(s[2 * jj],     qf[ka], b0, b1);
                mma16816(s[2 * jj + 1], qf[ka], b2, b3);
            }
        }

        // ---- tail exclusion for padding keys (exact: weight 0) ----
        if (kb + 64 > cnt1) {
#pragma unroll
            for (int j = 0; j < 8; j++) {
                int kc0 = kb + 8 * j + 2 * tig;
                if (kc0     >= cnt1) { s[j][0] = -1e30f; s[j][2] = -1e30f; }
                if (kc0 + 1 >= cnt1) { s[j][1] = -1e30f; s[j][3] = -1e30f; }
            }
        }

        // ---- online softmax ----
        float rm0 = -1e30f, rm1 = -1e30f;
#pragma unroll
        for (int j = 0; j < 8; j++) {
            rm0 = fmaxf(rm0, fmaxf(s[j][0], s[j][1]));
            rm1 = fmaxf(rm1, fmaxf(s[j][2], s[j][3]));
        }
        rm0 = fmaxf(rm0, __shfl_xor_sync(0xffffffffu, rm0, 1));
        rm0 = fmaxf(rm0, __shfl_xor_sync(0xffffffffu, rm0, 2));
        rm1 = fmaxf(rm1, __shfl_xor_sync(0xffffffffu, rm1, 1));
        rm1 = fmaxf(rm1, __shfl_xor_sync(0xffffffffu, rm1, 2));
        float mn0 = fmaxf(m0, rm0), mn1 = fmaxf(m1, rm1);
        float al0 = __expf(m0 - mn0), al1 = __expf(m1 - mn1);
        m0 = mn0; m1 = mn1;
        float rs0 = 0.f, rs1 = 0.f;
#pragma unroll
        for (int j = 0; j < 8; j++) {
            s[j][0] = __expf(s[j][0] - m0); rs0 += s[j][0];
            s[j][1] = __expf(s[j][1] - m0); rs0 += s[j][1];
            s[j][2] = __expf(s[j][2] - m1); rs1 += s[j][2];
            s[j][3] = __expf(s[j][3] - m1); rs1 += s[j][3];
        }
        rs0 += __shfl_xor_sync(0xffffffffu, rs0, 1);
        rs0 += __shfl_xor_sync(0xffffffffu, rs0, 2);
        rs1 += __shfl_xor_sync(0xffffffffu, rs1, 1);
        rs1 += __shfl_xor_sync(0xffffffffu, rs1, 2);
        l0 = l0 * al0 + rs0;
        l1 = l1 * al1 + rs1;
#pragma unroll
        for (int n = 0; n < 8; n++) {
            o[n][0] *= al0; o[n][1] *= al0; o[n][2] *= al1; o[n][3] *= al1;
        }

        // ---- O += P V (1-pass, ldmatrix.trans B-frags) ----
#pragma unroll
        for (int ka = 0; ka < 4; ka++) {
            const int j0 = 2 * ka, j1 = 2 * ka + 1;
            uint32_t ph[4];
            ph[0] = packh(__float2half_rn(s[j0][0]), __float2half_rn(s[j0][1]));
            ph[1] = packh(__float2half_rn(s[j0][2]), __float2half_rn(s[j0][3]));
            ph[2] = packh(__float2half_rn(s[j1][0]), __float2half_rn(s[j1][1]));
            ph[3] = packh(__float2half_rn(s[j1][2]), __float2half_rn(s[j1][3]));
            const uint32_t ksl = (uint32_t)(ka * 16 * SSTR * 2);
#pragma unroll
            for (int n = 0; n < 8; n++) {
                uint32_t b0, b1;
                ldsm_x2_t(b0, b1, vfb + ksl + 16 * n);
                mma16816(o[n], ph, b0, b1);
            }
        }
    }

    // ---- virtual tile: masked keys, all with score exactly 1e-9 ----
    float w0c = 0.f, w1c = 0.f, lf0 = l0, lf1 = l1;
    if (cnt0 > 0) {
        float mf0 = fmaxf(m0, 1e-9f);
        float mf1 = fmaxf(m1, 1e-9f);
        float sc0 = __expf(m0 - mf0);
        float sc1 = __expf(m1 - mf1);
        w0c = __expf(1e-9f - mf0);
        w1c = __expf(1e-9f - mf1);
        lf0 = l0 * sc0 + (float)cnt0 * w0c;
        lf1 = l1 * sc1 + (float)cnt0 * w1c;
#pragma unroll
        for (int n = 0; n < 8; n++) {
            o[n][0] *= sc0; o[n][1] *= sc0; o[n][2] *= sc1; o[n][3] *= sc1;
        }
    }

    // ---- epilogue: masked-V correction, normalize, fp16 store ----
    float inv0 = 1.f / lf0, inv1 = 1.f / lf1;
    int qr = q0 + 16 * w + g;
#pragma unroll
    for (int n = 0; n < 8; n++) {
        int col = cb + 8 * n + 2 * tig;
        float sv0 = sv[b * CDIM + col];
        float sv1 = sv[b * CDIM + col + 1];
        float a0 = (o[n][0] + w0c * sv0) * inv0;
        float a1 = (o[n][1] + w0c * sv1) * inv0;
        float a2 = (o[n][2] + w1c * sv0) * inv1;
        float a3 = (o[n][3] + w1c * sv1) * inv1;
        *(uint32_t*)&OF[(size_t)(b * CN + qr) * CDIM + col] =
            packh(__float2half_rn(a0), __float2half_rn(a1));
        *(uint32_t*)&OF[(size_t)(b * CN + qr + 8) * CDIM + col] =
            packh(__float2half_rn(a2), __float2half_rn(a3));
    }
}

// ---------------------------------------------------------------------------
extern "C" void kernel_launch(void* const* d_in, const int* in_sizes, int n_in,
                              void* d_out, int out_size)
{
    const float* x    = (const float*)d_in[0];
    const int*   mask = (const int*)  d_in[1];
    const float* W[4] = { (const float*)d_in[2], (const float*)d_in[3],
                          (const float*)d_in[4], (const float*)d_in[5] };
    float* out = (float*)d_out;

    h16 *xf, *qf, *kf, *vf, *of, *wf;
    int *idxl, *cnt;
    float *sv, *xmp;
    cudaGetSymbolAddress((void**)&xf, g_xf);
    cudaGetSymbolAddress((void**)&qf, g_qf);
    cudaGetSymbolAddress((void**)&kf, g_kf);
    cudaGetSymbolAddress((void**)&vf, g_vf);
    cudaGetSymbolAddress((void**)&of, g_of);
    cudaGetSymbolAddress((void**)&wf, g_wf);
    cudaGetSymbolAddress((void**)&idxl, g_idx);
    cudaGetSymbolAddress((void**)&cnt, g_cnt);
    cudaGetSymbolAddress((void**)&sv, g_sv);
    cudaGetSymbolAddress((void**)&xmp, g_xmp);

    const int M  = CB * CN;            // 8192
    const int NX = M * CDIM;
    const int NW = CDIM * CDIM;
    const int NB = (NX + 4 * NW) / 1024;  // 5120

    prep_all_kernel<<<NB + CB + 256, 256>>>(x, W[0], W[1], W[2], W[3], mask,
                                            xf, wf, idxl, cnt, xmp);

    const int gsm  = 3 * STAGE_B;                                       // 110592 B
    const int asmb = 3 * ASTG * (int)sizeof(h16) + 128 * SSTR * (int)sizeof(h16); // 73728 B
    cudaFuncSetAttribute(proj_gemm_kernel, cudaFuncAttributeMaxDynamicSharedMemorySize, gsm);
    cudaFuncSetAttribute(out_gemm_kernel, cudaFuncAttributeMaxDynamicSharedMemorySize, gsm);
    cudaFuncSetAttribute(attn_mma_kernel, cudaFuncAttributeMaxDynamicSharedMemorySize, asmb);

    proj_gemm_kernel<<<dim3(13, 64), 256, gsm>>>(
        xf,
        wf + 0 * (size_t)NW, wf + 1 * (size_t)NW, wf + 2 * (size_t)NW,
        W[2], xmp, idxl, cnt, qf, kf, vf, sv);

    attn_mma_kernel<<<dim3(CN / 128, CH * CB), 256, asmb>>>(
        qf, kf, vf, cnt, sv, of);

    out_gemm_kernel<<<dim3(4, M / 128), 256, gsm>>>(
        of, wf + 3 * (size_t)NW, out);
}